// round 5
// baseline (speedup 1.0000x reference)
#include <cuda_runtime.h>
#include <cstdint>
#include <cstddef>

#define BATCH 32
#define SEQT  2048
#define INSZ  512
#define HID   512
#define G3    1536
#define NB    128
#define NT    256
#define GSZ   32
typedef unsigned long long ull;

__device__ float g_xg[(size_t)SEQT * BATCH * G3];   // [t][b][3H]
__device__ float g_h[2][BATCH * HID];
__device__ unsigned g_bcount[4][32];                // per-group, 128B padded
__device__ unsigned g_bgen[4][32];

// ---- packed f32x2 helpers ----
__device__ __forceinline__ ull pk2(float x, float y) {
  ull r; asm("mov.b64 %0, {%1,%2};" : "=l"(r) : "f"(x), "f"(y)); return r;
}
__device__ __forceinline__ ull ffma2(ull a, ull b, ull c) {
  ull d; asm("fma.rn.f32x2 %0, %1, %2, %3;" : "=l"(d) : "l"(a), "l"(b), "l"(c)); return d;
}
__device__ __forceinline__ float2 upk2(ull v) {
  float x, y; asm("mov.b64 {%0,%1}, %2;" : "=f"(x), "=f"(y) : "l"(v));
  return make_float2(x, y);
}
__device__ __forceinline__ float sigmoid_f(float x) { return 1.f / (1.f + __expf(-x)); }
__device__ __forceinline__ float tanh_f(float x) {
  float e = __expf(-2.f * x); return (1.f - e) / (1.f + e);
}

// =============================================================
// Kernel A: x_gates = input @ W_ih^T + b_ih  (unchanged)
// =============================================================
__global__ __launch_bounds__(256, 2) void gemm_xgates(
    const float* __restrict__ A, const float* __restrict__ Wih,
    const float* __restrict__ bih) {
  __shared__ float As[16][128];
  __shared__ float Bs[16][128];
  const int tid = threadIdx.x;
  const int m0 = blockIdx.y << 7, n0 = blockIdx.x << 7;
  const int tx = tid & 15, ty = tid >> 4;
  const int lrow = tid & 127, lk = (tid >> 7) * 8;

  const float* Ap = A + (size_t)(m0 + lrow) * INSZ + lk;
  const float* Bp = Wih + (size_t)(n0 + lrow) * INSZ + lk;

  ull acc[4][8];
#pragma unroll
  for (int i = 0; i < 4; i++)
#pragma unroll
    for (int j = 0; j < 8; j++) acc[i][j] = 0ull;

  float4 la0 = *(const float4*)(Ap), la1 = *(const float4*)(Ap + 4);
  float4 lb0 = *(const float4*)(Bp), lb1 = *(const float4*)(Bp + 4);

  for (int kt = 0; kt < 32; kt++) {
    __syncthreads();
    As[lk + 0][lrow] = la0.x; As[lk + 1][lrow] = la0.y;
    As[lk + 2][lrow] = la0.z; As[lk + 3][lrow] = la0.w;
    As[lk + 4][lrow] = la1.x; As[lk + 5][lrow] = la1.y;
    As[lk + 6][lrow] = la1.z; As[lk + 7][lrow] = la1.w;
    Bs[lk + 0][lrow] = lb0.x; Bs[lk + 1][lrow] = lb0.y;
    Bs[lk + 2][lrow] = lb0.z; Bs[lk + 3][lrow] = lb0.w;
    Bs[lk + 4][lrow] = lb1.x; Bs[lk + 5][lrow] = lb1.y;
    Bs[lk + 6][lrow] = lb1.z; Bs[lk + 7][lrow] = lb1.w;
    __syncthreads();
    if (kt < 31) {
      Ap += 16; Bp += 16;
      la0 = *(const float4*)(Ap); la1 = *(const float4*)(Ap + 4);
      lb0 = *(const float4*)(Bp); lb1 = *(const float4*)(Bp + 4);
    }
#pragma unroll
    for (int k = 0; k < 16; k++) {
      ulonglong2 aA = *(const ulonglong2*)&As[k][ty * 4];
      ulonglong2 aB = *(const ulonglong2*)&As[k][64 + ty * 4];
      ull a2[4] = {aA.x, aA.y, aB.x, aB.y};
      float4 bfa = *(const float4*)&Bs[k][tx * 4];
      float4 bfb = *(const float4*)&Bs[k][64 + tx * 4];
      ull bd[8];
      bd[0] = pk2(bfa.x, bfa.x); bd[1] = pk2(bfa.y, bfa.y);
      bd[2] = pk2(bfa.z, bfa.z); bd[3] = pk2(bfa.w, bfa.w);
      bd[4] = pk2(bfb.x, bfb.x); bd[5] = pk2(bfb.y, bfb.y);
      bd[6] = pk2(bfb.z, bfb.z); bd[7] = pk2(bfb.w, bfb.w);
#pragma unroll
      for (int i = 0; i < 4; i++)
#pragma unroll
        for (int j = 0; j < 8; j++) acc[i][j] = ffma2(a2[i], bd[j], acc[i][j]);
    }
  }

  float4 bb0 = *(const float4*)(bih + n0 + tx * 4);
  float4 bb1 = *(const float4*)(bih + n0 + 64 + tx * 4);
  const float* bbp0 = &bb0.x; const float* bbp1 = &bb1.x;
#pragma unroll
  for (int i = 0; i < 8; i++) {
    int i2 = (i < 4) ? (i >> 1) : (2 + ((i - 4) >> 1));
    int half = i & 1;
    int m = m0 + ((i < 4) ? (ty * 4 + i) : (64 + ty * 4 + i - 4));
    int b = m >> 11, t = m & 2047;
    float* orow = g_xg + ((size_t)t * BATCH + b) * G3 + n0;
    float4 o0, o1; float2 p;
    p = upk2(acc[i2][0]); o0.x = (half ? p.y : p.x) + bbp0[0];
    p = upk2(acc[i2][1]); o0.y = (half ? p.y : p.x) + bbp0[1];
    p = upk2(acc[i2][2]); o0.z = (half ? p.y : p.x) + bbp0[2];
    p = upk2(acc[i2][3]); o0.w = (half ? p.y : p.x) + bbp0[3];
    p = upk2(acc[i2][4]); o1.x = (half ? p.y : p.x) + bbp1[0];
    p = upk2(acc[i2][5]); o1.y = (half ? p.y : p.x) + bbp1[1];
    p = upk2(acc[i2][6]); o1.z = (half ? p.y : p.x) + bbp1[2];
    p = upk2(acc[i2][7]); o1.w = (half ? p.y : p.x) + bbp1[3];
    *(float4*)(orow + tx * 4) = o0;
    *(float4*)(orow + 64 + tx * 4) = o1;
  }
}

// =============================================================
// Kernel B: batch-grouped persistent GRU scan
// =============================================================
__device__ __forceinline__ void group_barrier(int grp) {
  __syncthreads();
  if (threadIdx.x == 0) {
    unsigned* cnt = &g_bcount[grp][0];
    unsigned* gen = &g_bgen[grp][0];
    unsigned g0;
    asm volatile("ld.acquire.gpu.global.u32 %0,[%1];" : "=r"(g0) : "l"(gen) : "memory");
    unsigned a;
    asm volatile("atom.add.acq_rel.gpu.global.u32 %0,[%1],1;" : "=r"(a) : "l"(cnt) : "memory");
    if (a == GSZ - 1) {
      asm volatile("st.relaxed.gpu.global.u32 [%0],0;" :: "l"(cnt) : "memory");
      unsigned tmp;
      asm volatile("atom.add.release.gpu.global.u32 %0,[%1],1;" : "=r"(tmp) : "l"(gen) : "memory");
    } else {
      unsigned cur;
      do {
        asm volatile("ld.acquire.gpu.global.u32 %0,[%1];" : "=r"(cur) : "l"(gen) : "memory");
      } while (cur == g0);
    }
  }
  __syncthreads();
}

// smem byte layout:
//   WS  @ 0       : 48 rows * 2048B, row = [kh][kq? no: [kh][s][kq][16B]]  (96 KB)
//   HS  @ 98304   : [kh][s][kq][bb][16B]                                    (16 KB)
//   red @ 114688  : [8 warps][8 bb][12] floats                              (3 KB)
//   bh  @ 117760  : 48 floats
#define SCAN_SMEM 117952

__global__ __launch_bounds__(NT, 1) void gru_scan(
    const float* __restrict__ Whh, const float* __restrict__ bhh,
    const float* __restrict__ h0, float* __restrict__ out) {
  extern __shared__ char smem[];
  char* WS = smem;
  char* HS = smem + 98304;
  float* red = (float*)(smem + 114688);
  float* bh  = (float*)(smem + 117760);

  const int tid = threadIdx.x;
  const int grp = blockIdx.x >> 5;
  const int cid = blockIdx.x & 31;
  const int j0  = cid << 4;
  const int b0g = grp << 3;

  const int w = tid >> 5, lane = tid & 31;
  const int jp = w >> 1, kh = w & 1;
  const int bb = lane >> 2, kq = lane & 3;

  // --- load W_hh slice: smem row r = jj*3+gt <-> Whh row gt*512 + j0+jj ---
  // chunk (s,kq2) within a kh-half holds k-offset kq2*64 + s*4  (MATCHES h layout)
  for (int idx = tid; idx < 48 * 128; idx += NT) {
    int r = idx >> 7, c = idx & 127;
    int jj = r / 3, gt = r - jj * 3;
    float4 v = *(const float4*)(Whh + (size_t)(gt * HID + j0 + jj) * HID + (c << 2));
    int kh2 = c >> 6, rem = c & 63, kq2 = rem >> 4, s = rem & 15;
    *(float4*)(WS + r * 2048 + kh2 * 1024 + s * 64 + kq2 * 16) = v;
  }
  if (tid < 48) {
    int jj = tid / 3, gt = tid - jj * 3;
    bh[tid] = bhh[gt * HID + j0 + jj];
  }
  const int b_o = tid >> 4, jj_o = tid & 15;
  if (tid < 128)
    g_h[0][(b0g + b_o) * HID + j0 + jj_o] = h0[(b0g + b_o) * HID + j0 + jj_o];
  group_barrier(grp);

  for (int t = 0; t < SEQT; t++) {
    const float* hp = g_h[t & 1];
    float* hn = g_h[(t + 1) & 1];

    // prefetch per-output operands (threads 0..127)
    float xr = 0.f, xz = 0.f, xn = 0.f, hprev = 0.f;
    if (tid < 128) {
      const float* xgp = g_xg + ((size_t)t * BATCH + (b0g + b_o)) * G3 + j0 + jj_o;
      xr = __ldcg(xgp); xz = __ldcg(xgp + HID); xn = __ldcg(xgp + 2 * HID);
      hprev = __ldcg(hp + (b0g + b_o) * HID + j0 + jj_o);
    }

    // --- stage this group's h (16 KB) into HS, layout [kh][s][kq][bb][16B] ---
#pragma unroll
    for (int i = 0; i < 4; i++) {
      int idx = i * NT + tid;                       // 0..1023 float4s
      int hbb = idx & 7, hkq = (idx >> 3) & 3, hss = (idx >> 5) & 15, hkh = idx >> 9;
      int gk = hkh * 256 + hkq * 64 + hss * 4;
      const float* src = hp + (b0g + hbb) * HID + gk;
      float4 v;
      asm volatile("ld.global.cg.v4.f32 {%0,%1,%2,%3},[%4];"
                   : "=f"(v.x), "=f"(v.y), "=f"(v.z), "=f"(v.w) : "l"(src));
      *(float4*)(HS + idx * 16) = v;
    }
    __syncthreads();

    // --- preload this lane's 64 h floats into regs ---
    ull hx[16], hy[16];
    const char* hb = HS + kh * 8192 + kq * 128 + bb * 16;
#pragma unroll
    for (int s = 0; s < 16; s++) {
      ulonglong2 u = *(const ulonglong2*)(hb + s * 512);
      hx[s] = u.x; hy[s] = u.y;
    }

    // --- 12 rows x 1 batch x 64 k per lane, FFMA2 ---
    ull acc[12];
#pragma unroll
    for (int r = 0; r < 12; r++) acc[r] = 0ull;
    const char* wb = WS + (jp * 12) * 2048 + kh * 1024 + kq * 16;
#pragma unroll
    for (int s = 0; s < 16; s++) {
      const char* wbs = wb + s * 64;
#pragma unroll
      for (int r = 0; r < 12; r++) {
        ulonglong2 u = *(const ulonglong2*)(wbs + r * 2048);
        acc[r] = ffma2(u.x, hx[s], acc[r]);
        acc[r] = ffma2(u.y, hy[s], acc[r]);
      }
    }

    // --- reduce over kq (2 shuffles), stash per (warp, bb) ---
#pragma unroll
    for (int r = 0; r < 12; r++) {
      float2 p = upk2(acc[r]);
      float v = p.x + p.y;
      v += __shfl_xor_sync(0xffffffffu, v, 1);
      v += __shfl_xor_sync(0xffffffffu, v, 2);
      if (kq == 0) red[(w * 8 + bb) * 12 + r] = v;
    }
    __syncthreads();

    // --- gate math (threads 0..127: one (b, j) each) ---
    if (tid < 128) {
      int jp_o = jj_o >> 2, jj2 = jj_o & 3;
      int ba0 = ((jp_o * 2 + 0) * 8 + b_o) * 12 + jj2 * 3;
      int ba1 = ((jp_o * 2 + 1) * 8 + b_o) * 12 + jj2 * 3;
      float sr = red[ba0 + 0] + red[ba1 + 0];
      float sz = red[ba0 + 1] + red[ba1 + 1];
      float sn = red[ba0 + 2] + red[ba1 + 2];
      float rg = sigmoid_f(xr + sr + bh[jj_o * 3 + 0]);
      float zg = sigmoid_f(xz + sz + bh[jj_o * 3 + 1]);
      float ng = tanh_f(xn + rg * (sn + bh[jj_o * 3 + 2]));
      float hnew = ng + zg * (hprev - ng);
      hn[(b0g + b_o) * HID + j0 + jj_o] = hnew;
      out[((size_t)(b0g + b_o) * SEQT + t) * HID + j0 + jj_o] = hnew;
    }
    group_barrier(grp);
  }
}

extern "C" void kernel_launch(void* const* d_in, const int* in_sizes, int n_in,
                              void* d_out, int out_size) {
  (void)in_sizes; (void)n_in; (void)out_size;
  const float* input = (const float*)d_in[0];
  const float* h0    = (const float*)d_in[1];
  const float* wih   = (const float*)d_in[2];
  const float* whh   = (const float*)d_in[3];
  const float* bih   = (const float*)d_in[4];
  const float* bhh   = (const float*)d_in[5];
  float* out = (float*)d_out;

  cudaFuncSetAttribute(gru_scan, cudaFuncAttributeMaxDynamicSharedMemorySize, SCAN_SMEM);

  dim3 gA(G3 / 128, (BATCH * SEQT) / 128);
  gemm_xgates<<<gA, 256>>>(input, wih, bih);
  gru_scan<<<NB, NT, SCAN_SMEM>>>(whh, bhh, h0, out);
}